// round 7
// baseline (speedup 1.0000x reference)
#include <cuda_runtime.h>
#include <cuda_fp16.h>
#include <math.h>

// ---------------- problem constants ----------------
#define NQ      32768      // BATCH*2 query rows
#define D       128
#define G4      1024       // gate width (interleaved: cg = 4*j + gate)
#define FEW     5
#define SST     136        // smem stride (halfs) for GEMM tiles: conflict-free

// k_step smem layout (bytes)
#define OFF_AS   0
#define OFF_BS   17408                  // As: 64*136*2
#define OFF_SC   (17408 + 69632)        // Bs: 256*136*2
#define OFF_SS2  (OFF_SC + 17408)       // sC: 64*68*4
#define OFF_SAT  (OFF_SS2 + 5120)       // sS2: 5*256*4
#define SMEM_STEP (OFF_SAT + 1280)      // sAttn: 64*5*4  => 110848 total
#define SMEM_G0  (2 * 128 * SST * 2)    // Gbuf gemm: 69632

// ---------------- scratch (static device arrays; no allocation) ----------------
__device__ float  d_SG[FEW * D];                 // support_g (5 x 128)
__device__ float  d_S2[FEW * G4];                // SG @ W_hh[:,128:].T, interleaved cols
__device__ float  d_MS[D];                       // mean_support
__device__ float  d_q    [(size_t)NQ * D];       // gathered query embeddings (fp32)
__device__ __half d_q16  [(size_t)NQ * D];       // fp16 q for Gbuf GEMM
__device__ __half d_hl16a[(size_t)NQ * D];       // hl ping (init: -q for step-0 trick)
__device__ __half d_hl16b[(size_t)NQ * D];       // hl pong
__device__ float  d_hl   [(size_t)NQ * D];       // fp32 hl (last step only)
__device__ float  d_Gbuf [(size_t)NQ * G4];      // G01 = q@(Wih+W1).T + bsum (interleaved)
__device__ float  d_c    [(size_t)NQ * 256];     // LSTM cell state
__device__ float  d_attn [(size_t)NQ * 8];       // attention weights (5, padded 8)
__device__ __half d_Wc16[G4 * D];                // Wih + Whh[:,:128], fp16, interleaved rows
__device__ __half d_W116[G4 * D];                // Whh[:,:128],       fp16, interleaved rows
__device__ float  d_bsum[G4];                    // b_ih + b_hh, interleaved

__device__ __forceinline__ float sigf(float x) { return 1.0f / (1.0f + expf(-x)); }

__device__ __forceinline__ void mma_f16(float* c, const unsigned* a, unsigned b0, unsigned b1) {
    asm volatile(
        "mma.sync.aligned.m16n8k16.row.col.f32.f16.f16.f32 "
        "{%0,%1,%2,%3}, {%4,%5,%6,%7}, {%8,%9}, {%0,%1,%2,%3};"
        : "+f"(c[0]), "+f"(c[1]), "+f"(c[2]), "+f"(c[3])
        : "r"(a[0]), "r"(a[1]), "r"(a[2]), "r"(a[3]), "r"(b0), "r"(b1));
}

// ---------------- prep: fp16 weight packs (gate-interleaved) / bsum ----------------
__global__ void k_wsum(const float* __restrict__ Wih, const float* __restrict__ Whh,
                       const float* __restrict__ bih, const float* __restrict__ bhh) {
    int idx = blockIdx.x * 256 + threadIdx.x;           // 1024*128
    int cg = idx >> 7, k = idx & 127;
    int j = cg >> 2, gate = cg & 3;
    int orig = gate * 256 + j;                          // original gate row
    float w1 = Whh[(size_t)orig * 256 + k];
    d_Wc16[idx] = __float2half_rn(Wih[(size_t)orig * 128 + k] + w1);
    d_W116[idx] = __float2half_rn(w1);
    if (idx < G4) {
        int jj = idx >> 2, gg = idx & 3;
        int o2 = gg * 256 + jj;
        d_bsum[idx] = bih[o2] + bhh[o2];
    }
}

// ---------------- support path: GCN (linear!) + MLP + LayerNorm ----------------
__global__ void k_support(const int* __restrict__ sp, const float* __restrict__ emb,
                          const float* __restrict__ gW, const float* __restrict__ gb,
                          const float* __restrict__ p1W, const float* __restrict__ p1b,
                          const float* __restrict__ p2W, const float* __restrict__ p2b,
                          const float* __restrict__ lng, const float* __restrict__ lnb) {
    __shared__ float cs[256], s[128], h1[256], x[128], stat[2];
    int f = blockIdx.x, t = threadIdx.x;
    int side = t >> 7, col = t & 127;
    const int* pf = sp + f * 400;
    float acc = 0.f;
    #pragma unroll 4
    for (int n = 0; n < 200; n++) {
        int idx = pf[n * 2 + side];
        acc += emb[(size_t)idx * 128 + col];
    }
    cs[t] = acc;
    __syncthreads();
    if (t < 128) {
        float a = 200.f * gb[t];
        #pragma unroll 4
        for (int k = 0; k < 256; k++) a = fmaf(cs[k], gW[t * 256 + k], a);
        s[t] = tanhf(a * 0.2f);
    }
    __syncthreads();
    {
        float a = p1b[t];
        #pragma unroll 4
        for (int j = 0; j < 128; j++) a = fmaf(s[j], p1W[t * 128 + j], a);
        h1[t] = fmaxf(a, 0.f);
    }
    __syncthreads();
    if (t < 128) {
        float a = p2b[t];
        #pragma unroll 4
        for (int k = 0; k < 256; k++) a = fmaf(h1[k], p2W[t * 256 + k], a);
        x[t] = a + s[t];
    }
    __syncthreads();
    if (t == 0) {
        float mu = 0.f;
        for (int j = 0; j < 128; j++) mu += x[j];
        mu *= (1.f / 128.f);
        float v = 0.f;
        for (int j = 0; j < 128; j++) { float dd = x[j] - mu; v += dd * dd; }
        v *= (1.f / 128.f);
        stat[0] = mu; stat[1] = rsqrtf(v + 1e-5f);
    }
    __syncthreads();
    if (t < 128) d_SG[f * 128 + t] = lng[t] * (x[t] - stat[0]) * stat[1] + lnb[t];
}

// ---------------- S2 = SG @ W_hh[:,128:].T (interleaved cols) + mean_support ----------------
__global__ void k_s2mean(const float* __restrict__ Whh) {
    __shared__ float sg[128];
    int b = blockIdx.x, t = threadIdx.x;
    if (b < 40) {
        int f = b >> 3, gbk = b & 7;
        sg[t] = d_SG[f * 128 + t];
        __syncthreads();
        int cg = gbk * 128 + t;
        int j = cg >> 2, gate = cg & 3;
        int orig = gate * 256 + j;
        float a = 0.f;
        #pragma unroll 4
        for (int jj = 0; jj < 128; jj++) a = fmaf(sg[jj], Whh[(size_t)orig * 256 + 128 + jj], a);
        d_S2[f * G4 + cg] = a;
    } else {
        float a = 0.f;
        #pragma unroll
        for (int f = 0; f < FEW; f++) a += d_SG[f * 128 + t];
        d_MS[t] = a * 0.2f;
    }
}

// ---------------- gather q = emb[query_pairs]; q16; hl16a = -q (step-0 trick) ----------------
__global__ void k_gather(const int* __restrict__ qp, const float* __restrict__ emb) {
    int row = blockIdx.x * 8 + (threadIdx.x >> 5);
    int lane = threadIdx.x & 31;
    int idx = qp[row];
    float4 v = *(const float4*)(emb + (size_t)idx * 128 + lane * 4);
    *(float4*)(d_q + (size_t)row * 128 + lane * 4) = v;
    *(__half2*)(d_q16   + (size_t)row * 128 + lane * 4)     = __floats2half2_rn(v.x, v.y);
    *(__half2*)(d_q16   + (size_t)row * 128 + lane * 4 + 2) = __floats2half2_rn(v.z, v.w);
    *(__half2*)(d_hl16a + (size_t)row * 128 + lane * 4)     = __floats2half2_rn(-v.x, -v.y);
    *(__half2*)(d_hl16a + (size_t)row * 128 + lane * 4 + 2) = __floats2half2_rn(-v.z, -v.w);
}

// ---------------- Gbuf precompute GEMM: 128x128 tile, K=128 (R6-style, mode-0 only) ----------------
__global__ void __launch_bounds__(256) k_gemm0(const __half* __restrict__ A,
                                               const __half* __restrict__ B,
                                               const float* __restrict__ bias) {
    extern __shared__ __half sm[];
    __half* As = sm;
    __half* Bs = sm + 128 * SST;
    int tid = threadIdx.x, lane = tid & 31, warp = tid >> 5;
    int g = lane >> 2, tg = lane & 3;
    int wm = warp >> 2, wn = warp & 3;
    int bx = blockIdx.x, by = blockIdx.y;
    int colblk = bx * 128;
    const __half* Ag = A + (size_t)by * 128 * 128;
    const __half* Bg = B + (size_t)colblk * 128;

    #pragma unroll
    for (int it = 0; it < 8; it++) {
        int idx = tid + it * 256;
        int r = idx >> 4, c8 = (idx & 15) << 3;
        *(uint4*)(As + r * SST + c8) = *(const uint4*)(Ag + r * 128 + c8);
        *(uint4*)(Bs + r * SST + c8) = *(const uint4*)(Bg + r * 128 + c8);
    }
    __syncthreads();

    float acc[4][4][4];
    #pragma unroll
    for (int mi = 0; mi < 4; mi++)
        #pragma unroll
        for (int ni = 0; ni < 4; ni++)
            #pragma unroll
            for (int r = 0; r < 4; r++) acc[mi][ni][r] = 0.f;

    #pragma unroll
    for (int kk = 0; kk < 8; kk++) {
        int c0 = kk * 16 + 2 * tg;
        unsigned a[4][4];
        #pragma unroll
        for (int mi = 0; mi < 4; mi++) {
            const __half* p = As + (wm * 64 + mi * 16 + g) * SST + c0;
            a[mi][0] = *(const unsigned*)(p);
            a[mi][1] = *(const unsigned*)(p + 8 * SST);
            a[mi][2] = *(const unsigned*)(p + 8);
            a[mi][3] = *(const unsigned*)(p + 8 * SST + 8);
        }
        #pragma unroll
        for (int ni = 0; ni < 4; ni++) {
            const __half* p = Bs + (wn * 32 + ni * 8 + g) * SST + c0;
            unsigned b0 = *(const unsigned*)(p);
            unsigned b1 = *(const unsigned*)(p + 8);
            #pragma unroll
            for (int mi = 0; mi < 4; mi++)
                mma_f16(acc[mi][ni], a[mi], b0, b1);
        }
    }

    #pragma unroll
    for (int mi = 0; mi < 4; mi++) {
        #pragma unroll
        for (int ni = 0; ni < 4; ni++) {
            int row0 = by * 128 + wm * 64 + mi * 16 + g;
            int cit = wn * 32 + ni * 8 + 2 * tg;
            float2 bv = *(const float2*)(bias + colblk + cit);
            *(float2*)(d_Gbuf + (size_t)row0 * G4 + colblk + cit) =
                make_float2(acc[mi][ni][0] + bv.x, acc[mi][ni][1] + bv.y);
            *(float2*)(d_Gbuf + (size_t)(row0 + 8) * G4 + colblk + cit) =
                make_float2(acc[mi][ni][2] + bv.x, acc[mi][ni][3] + bv.y);
        }
    }
}

// ---------------- fused step: GEMM (64x256, K=128) + LSTM cell update ----------------
// gates(row, cg) = Ain@W1.T + Gbuf [+ attn@S2]; cg = 4j+g interleaved so the
// (i,f,g,o) quadruple for cell j is lane-pair-local -> 2 shuffles per fragment.
// strip s covers j in [s*64, s*64+64) i.e. gate cols [s*256, s*256+256).
__global__ void __launch_bounds__(256) k_step(const __half* __restrict__ Ain,
                                              __half* __restrict__ hlout,
                                              int first, int hasattn, int last) {
    extern __shared__ char smraw[];
    __half* As = (__half*)(smraw + OFF_AS);
    __half* Bs = (__half*)(smraw + OFF_BS);
    float* sC  = (float*)(smraw + OFF_SC);
    float* sS2 = (float*)(smraw + OFF_SS2);
    float* sAt = (float*)(smraw + OFF_SAT);
    float* sHL = (float*)(smraw + OFF_AS);     // alias As after MMA

    int s = blockIdx.x, by = blockIdx.y;
    int tid = threadIdx.x, lane = tid & 31, warp = tid >> 5;
    int g = lane >> 2, tg = lane & 3;
    int wm = warp >> 2, wn = warp & 3;         // 2(M) x 4(N); warp tile 32 x 64

    const __half* Ag = Ain + (size_t)by * 64 * 128;
    const __half* Bg = d_W116 + (size_t)s * 256 * 128;

    #pragma unroll
    for (int it = 0; it < 4; it++) {
        int i = tid + it * 256; int r = i >> 4, c8 = (i & 15) << 3;
        *(uint4*)(As + r * SST + c8) = *(const uint4*)(Ag + r * 128 + c8);
    }
    #pragma unroll
    for (int it = 0; it < 16; it++) {
        int i = tid + it * 256; int r = i >> 4, c8 = (i & 15) << 3;
        *(uint4*)(Bs + r * SST + c8) = *(const uint4*)(Bg + r * 128 + c8);
    }
    if (!first) {
        #pragma unroll
        for (int it = 0; it < 4; it++) {
            int i = tid + it * 256; int r = i >> 4, c4 = (i & 15) << 2;
            *(float4*)(sC + r * 68 + c4) =
                *(const float4*)(d_c + (size_t)(by * 64 + r) * 256 + s * 64 + c4);
        }
    }
    if (hasattn) {
        for (int i = tid; i < FEW * 256; i += 256)
            sS2[i] = d_S2[(i >> 8) * G4 + s * 256 + (i & 255)];
        for (int i = tid; i < 64 * FEW; i += 256) {
            int r = i / FEW, f = i - r * FEW;
            sAt[i] = d_attn[(size_t)(by * 64 + r) * 8 + f];
        }
    }
    __syncthreads();

    float acc[2][8][4];
    #pragma unroll
    for (int mi = 0; mi < 2; mi++)
        #pragma unroll
        for (int ni = 0; ni < 8; ni++)
            #pragma unroll
            for (int r = 0; r < 4; r++) acc[mi][ni][r] = 0.f;

    #pragma unroll
    for (int kk = 0; kk < 8; kk++) {
        int c0 = kk * 16 + 2 * tg;
        unsigned a[2][4];
        #pragma unroll
        for (int mi = 0; mi < 2; mi++) {
            const __half* p = As + (wm * 32 + mi * 16 + g) * SST + c0;
            a[mi][0] = *(const unsigned*)(p);
            a[mi][1] = *(const unsigned*)(p + 8 * SST);
            a[mi][2] = *(const unsigned*)(p + 8);
            a[mi][3] = *(const unsigned*)(p + 8 * SST + 8);
        }
        #pragma unroll
        for (int ni = 0; ni < 8; ni++) {
            const __half* p = Bs + (wn * 64 + ni * 8 + g) * SST + c0;
            unsigned b0 = *(const unsigned*)(p);
            unsigned b1 = *(const unsigned*)(p + 8);
            #pragma unroll
            for (int mi = 0; mi < 2; mi++)
                mma_f16(acc[mi][ni], a[mi], b0, b1);
        }
    }
    __syncthreads();                            // As dead -> sHL writable

    bool evenl = (tg & 1) == 0;
    bool dohl = (s < 2);
    #pragma unroll
    for (int mi = 0; mi < 2; mi++) {
        #pragma unroll
        for (int ni = 0; ni < 8; ni++) {
            int rl0 = wm * 32 + mi * 16 + g;
            int col = wn * 64 + ni * 8 + 2 * tg;
            int jl = col >> 2;
            #pragma unroll
            for (int rr = 0; rr < 2; rr++) {
                int rl = rl0 + rr * 8;
                size_t row = (size_t)(by * 64 + rl);
                float2 gv = *(const float2*)(d_Gbuf + row * G4 + s * 256 + col);
                float x0 = acc[mi][ni][rr * 2 + 0] + gv.x;
                float x1 = acc[mi][ni][rr * 2 + 1] + gv.y;
                if (hasattn) {
                    #pragma unroll
                    for (int f = 0; f < FEW; f++) {
                        float av = sAt[rl * FEW + f];
                        x0 = fmaf(av, sS2[f * 256 + col], x0);
                        x1 = fmaf(av, sS2[f * 256 + col + 1], x1);
                    }
                }
                // even lanes: (x0,x1) = (pre_i, pre_f); odd: (pre_g, pre_o)
                float s0 = sigf(x0);
                float s1 = sigf(x1);
                float t0 = tanhf(x0);
                float tgn = __shfl_xor_sync(0xffffffffu, t0, 1);  // even <- odd's tanh(g)
                float cn = 0.f;
                if (evenl) {
                    float cp = first ? 0.f : sC[rl * 68 + jl];
                    cn = fmaf(s1, cp, s0 * tgn);
                    sC[rl * 68 + jl] = cn;
                }
                float cx = __shfl_xor_sync(0xffffffffu, cn, 1);   // odd <- even's cn
                if (!evenl && dohl)
                    sHL[rl * 68 + jl] = s1 * tanhf(cx);           // sig(o)*tanh(cn)
            }
        }
    }
    __syncthreads();

    if (!last) {
        #pragma unroll
        for (int it = 0; it < 4; it++) {
            int i = tid + it * 256; int r = i >> 4, c4 = (i & 15) << 2;
            *(float4*)(d_c + (size_t)(by * 64 + r) * 256 + s * 64 + c4) =
                *(const float4*)(sC + r * 68 + c4);
        }
    }
    if (dohl) {
        if (!last) {
            #pragma unroll
            for (int it = 0; it < 8; it++) {
                int i = tid + it * 256; int r = i >> 5, c2 = (i & 31) << 1;
                __half2 h = __floats2half2_rn(sHL[r * 68 + c2], sHL[r * 68 + c2 + 1]);
                *(__half2*)(hlout + (size_t)(by * 64 + r) * 128 + s * 64 + c2) = h;
            }
        } else {
            #pragma unroll
            for (int it = 0; it < 4; it++) {
                int i = tid + it * 256; int r = i >> 4, c4 = (i & 15) << 2;
                *(float4*)(d_hl + (size_t)(by * 64 + r) * 128 + s * 64 + c4) =
                    *(const float4*)(sHL + r * 68 + c4);
            }
        }
    }
}

// ---------------- attention logits + softmax (per step) ----------------
__global__ void __launch_bounds__(256) k_attn(const __half* __restrict__ hl) {
    __shared__ float sSg[FEW * 128];
    for (int i = threadIdx.x; i < FEW * 128; i += 256) sSg[i] = d_SG[i];
    __syncthreads();
    int row = blockIdx.x * 8 + (threadIdx.x >> 5);
    int lane = threadIdx.x & 31;
    float part[FEW] = {0.f, 0.f, 0.f, 0.f, 0.f};
    #pragma unroll
    for (int k = 0; k < 4; k++) {
        int j = lane + 32 * k;
        float hq = d_q[(size_t)row * 128 + j] + __half2float(hl[(size_t)row * 128 + j]);
        #pragma unroll
        for (int f = 0; f < FEW; f++) part[f] = fmaf(hq, sSg[f * 128 + j], part[f]);
    }
    #pragma unroll
    for (int o = 16; o; o >>= 1)
        #pragma unroll
        for (int f = 0; f < FEW; f++) part[f] += __shfl_xor_sync(0xffffffffu, part[f], o);
    if (lane == 0) {
        float m = part[0];
        #pragma unroll
        for (int f = 1; f < FEW; f++) m = fmaxf(m, part[f]);
        float e[FEW], ss = 0.f;
        #pragma unroll
        for (int f = 0; f < FEW; f++) { e[f] = expf(part[f] - m); ss += e[f]; }
        float inv = 1.f / ss;
        #pragma unroll
        for (int f = 0; f < FEW; f++) d_attn[(size_t)row * 8 + f] = e[f] * inv;
    }
}

// ---------------- final: out[b] = mean(hq[2b], hq[2b+1]) . mean_support ----------------
__global__ void k_final(float* __restrict__ out) {
    __shared__ float ms[128];
    int t = threadIdx.x;
    if (t < 128) ms[t] = d_MS[t];
    __syncthreads();
    int b = blockIdx.x * 8 + (t >> 5);
    int lane = t & 31;
    const float* q0 = d_q  + (size_t)b * 256;
    const float* h0 = d_hl + (size_t)b * 256;
    int j = lane * 4;
    float4 qa = *(const float4*)(q0 + j);
    float4 qb = *(const float4*)(q0 + 128 + j);
    float4 ha = *(const float4*)(h0 + j);
    float4 hb = *(const float4*)(h0 + 128 + j);
    float4 m4 = *(const float4*)(ms + j);
    float p = 0.5f * ((qa.x + ha.x + qb.x + hb.x) * m4.x +
                      (qa.y + ha.y + qb.y + hb.y) * m4.y +
                      (qa.z + ha.z + qb.z + hb.z) * m4.z +
                      (qa.w + ha.w + qb.w + hb.w) * m4.w);
    #pragma unroll
    for (int o = 16; o; o >>= 1) p += __shfl_xor_sync(0xffffffffu, p, o);
    if (lane == 0) out[b] = p;
}

// ---------------- launcher ----------------
extern "C" void kernel_launch(void* const* d_in, const int* in_sizes, int n_in,
                              void* d_out, int out_size) {
    const int*   qp  = (const int*)d_in[0];
    const int*   sp  = (const int*)d_in[1];
    const float* emb = (const float*)d_in[2];
    const float* gW  = (const float*)d_in[3];
    const float* gb  = (const float*)d_in[4];
    const float* p1W = (const float*)d_in[5];
    const float* p1b = (const float*)d_in[6];
    const float* p2W = (const float*)d_in[7];
    const float* p2b = (const float*)d_in[8];
    const float* lng = (const float*)d_in[9];
    const float* lnb = (const float*)d_in[10];
    const float* Wih = (const float*)d_in[11];
    const float* Whh = (const float*)d_in[12];
    const float* bih = (const float*)d_in[13];
    const float* bhh = (const float*)d_in[14];
    float* out = (float*)d_out;

    static int attr_set = 0;
    if (!attr_set) {
        cudaFuncSetAttribute(k_gemm0, cudaFuncAttributeMaxDynamicSharedMemorySize, SMEM_G0);
        cudaFuncSetAttribute(k_step,  cudaFuncAttributeMaxDynamicSharedMemorySize, SMEM_STEP);
        attr_set = 1;
    }

    k_wsum<<<512, 256>>>(Wih, Whh, bih, bhh);
    k_support<<<5, 256>>>(sp, emb, gW, gb, p1W, p1b, p2W, p2b, lng, lnb);
    k_s2mean<<<41, 128>>>(Whh);
    k_gather<<<NQ / 8, 256>>>(qp, emb);

    __half* pQ16; cudaGetSymbolAddress((void**)&pQ16, d_q16);
    __half* pA;   cudaGetSymbolAddress((void**)&pA,   d_hl16a);
    __half* pB;   cudaGetSymbolAddress((void**)&pB,   d_hl16b);
    __half* pWc;  cudaGetSymbolAddress((void**)&pWc,  d_Wc16);
    float*  pBs;  cudaGetSymbolAddress((void**)&pBs,  d_bsum);

    // Gbuf = q @ (Wih + W1).T + bsum  (interleaved gate cols)
    k_gemm0<<<dim3(8, NQ / 128), 256, SMEM_G0>>>(pQ16, pWc, pBs);

    dim3 gS(4, NQ / 64);    // 4 j-strips x 512 row-blocks
    dim3 gSL(2, NQ / 64);   // last step: j<128 only

    // step 0: gates = Gbuf + (-q)@W1.T; c=0; no attn term
    k_step<<<gS, 256, SMEM_STEP>>>(pA, pB, 1, 0, 0);
    k_attn<<<NQ / 8, 256>>>(pB);
    // step 1
    k_step<<<gS, 256, SMEM_STEP>>>(pB, pA, 0, 1, 0);
    k_attn<<<NQ / 8, 256>>>(pA);
    // step 2
    k_step<<<gS, 256, SMEM_STEP>>>(pA, pB, 0, 1, 0);
    k_attn<<<NQ / 8, 256>>>(pB);
    // step 3 (last): only j<128, writes fp32 d_hl, no c store
    k_step<<<gSL, 256, SMEM_STEP>>>(pB, pA, 0, 1, 1);

    k_final<<<16384 / 8, 256>>>(out);
}

// round 8
// speedup vs baseline: 1.2162x; 1.2162x over previous
#include <cuda_runtime.h>
#include <cuda_fp16.h>
#include <math.h>

// ---------------- problem constants ----------------
#define NQ      32768      // BATCH*2 query rows
#define D       128
#define G4      1024       // gate width (original order: i|f|g|o blocks of 256)
#define FEW     5
#define SST     136        // smem stride (halfs): conflict-free fragment banks

// k_gates smem layout (bytes): As 34816 | Bs 34816 | sS2 20480 | sAt 2560 | sBias 4096
#define OFF_BS    34816
#define OFF_SS2   69632
#define OFF_SAT   90112
#define OFF_BIAS  92672
#define SMEM_GATES 96768

// ---------------- scratch (static device arrays; no allocation) ----------------
__device__ float  d_SG[FEW * D];                 // support_g (5 x 128)
__device__ float  d_S2[FEW * G4];                // SG @ W_hh[:,128:].T
__device__ float  d_MS[D];                       // mean_support
__device__ float  d_q   [(size_t)NQ * D];        // gathered query embeddings (fp32)
__device__ __half d_q16 [(size_t)NQ * D];        // fp16 q
__device__ __half d_hl16[(size_t)NQ * D];        // hl fp16 (init -q; rewritten each step)
__device__ float  d_hl  [(size_t)NQ * D];        // fp32 hl (last step only)
__device__ __half d_Gbuf[(size_t)NQ * G4];       // G01 = q@(Wih+W1).T + bsum   (fp16)
__device__ __half d_gates[(size_t)NQ * G4];      // per-step gates               (fp16)
__device__ float  d_c   [(size_t)NQ * 256];      // LSTM cell state (fp32)
__device__ float  d_attn[(size_t)NQ * 8];        // attention weights (5, padded 8)
__device__ __half d_Wc16[G4 * D];                // Wih + Whh[:,:128] (fp16)
__device__ __half d_W116[G4 * D];                // Whh[:,:128]       (fp16)
__device__ float  d_bsum[G4];                    // b_ih + b_hh

__device__ __forceinline__ float sigf(float x) { return 1.0f / (1.0f + expf(-x)); }

__device__ __forceinline__ void mma_f16(float* c, const unsigned* a, unsigned b0, unsigned b1) {
    asm volatile(
        "mma.sync.aligned.m16n8k16.row.col.f32.f16.f16.f32 "
        "{%0,%1,%2,%3}, {%4,%5,%6,%7}, {%8,%9}, {%0,%1,%2,%3};"
        : "+f"(c[0]), "+f"(c[1]), "+f"(c[2]), "+f"(c[3])
        : "r"(a[0]), "r"(a[1]), "r"(a[2]), "r"(a[3]), "r"(b0), "r"(b1));
}

// ---------------- prep: fp16 weight packs / bsum ----------------
__global__ void k_wsum(const float* __restrict__ Wih, const float* __restrict__ Whh,
                       const float* __restrict__ bih, const float* __restrict__ bhh) {
    int idx = blockIdx.x * 256 + threadIdx.x;           // 1024*128
    int r = idx >> 7, k = idx & 127;
    float w1 = Whh[(size_t)r * 256 + k];
    d_Wc16[idx] = __float2half_rn(Wih[idx] + w1);
    d_W116[idx] = __float2half_rn(w1);
    if (idx < G4) d_bsum[idx] = bih[idx] + bhh[idx];
}

// ---------------- support path: GCN (linear!) + MLP + LayerNorm ----------------
__global__ void k_support(const int* __restrict__ sp, const float* __restrict__ emb,
                          const float* __restrict__ gW, const float* __restrict__ gb,
                          const float* __restrict__ p1W, const float* __restrict__ p1b,
                          const float* __restrict__ p2W, const float* __restrict__ p2b,
                          const float* __restrict__ lng, const float* __restrict__ lnb) {
    __shared__ float cs[256], s[128], h1[256], x[128], stat[2];
    int f = blockIdx.x, t = threadIdx.x;
    int side = t >> 7, col = t & 127;
    const int* pf = sp + f * 400;
    float acc = 0.f;
    #pragma unroll 4
    for (int n = 0; n < 200; n++) {
        int idx = pf[n * 2 + side];
        acc += emb[(size_t)idx * 128 + col];
    }
    cs[t] = acc;
    __syncthreads();
    if (t < 128) {
        float a = 200.f * gb[t];
        #pragma unroll 4
        for (int k = 0; k < 256; k++) a = fmaf(cs[k], gW[t * 256 + k], a);
        s[t] = tanhf(a * 0.2f);
    }
    __syncthreads();
    {
        float a = p1b[t];
        #pragma unroll 4
        for (int j = 0; j < 128; j++) a = fmaf(s[j], p1W[t * 128 + j], a);
        h1[t] = fmaxf(a, 0.f);
    }
    __syncthreads();
    if (t < 128) {
        float a = p2b[t];
        #pragma unroll 4
        for (int k = 0; k < 256; k++) a = fmaf(h1[k], p2W[t * 256 + k], a);
        x[t] = a + s[t];
    }
    __syncthreads();
    if (t == 0) {
        float mu = 0.f;
        for (int j = 0; j < 128; j++) mu += x[j];
        mu *= (1.f / 128.f);
        float v = 0.f;
        for (int j = 0; j < 128; j++) { float dd = x[j] - mu; v += dd * dd; }
        v *= (1.f / 128.f);
        stat[0] = mu; stat[1] = rsqrtf(v + 1e-5f);
    }
    __syncthreads();
    if (t < 128) d_SG[f * 128 + t] = lng[t] * (x[t] - stat[0]) * stat[1] + lnb[t];
}

// ---------------- S2 = SG @ W_hh[:,128:].T + mean_support ----------------
__global__ void k_s2mean(const float* __restrict__ Whh) {
    __shared__ float sg[128];
    int b = blockIdx.x, t = threadIdx.x;
    if (b < 40) {
        int f = b >> 3, gbk = b & 7;
        sg[t] = d_SG[f * 128 + t];
        __syncthreads();
        int g = gbk * 128 + t;
        float a = 0.f;
        #pragma unroll 4
        for (int j = 0; j < 128; j++) a = fmaf(sg[j], Whh[(size_t)g * 256 + 128 + j], a);
        d_S2[f * G4 + g] = a;
    } else {
        float a = 0.f;
        #pragma unroll
        for (int f = 0; f < FEW; f++) a += d_SG[f * 128 + t];
        d_MS[t] = a * 0.2f;
    }
}

// ---------------- gather q; q16; hl16 = -q (step-0 trick, re-init every call) ----------------
__global__ void k_gather(const int* __restrict__ qp, const float* __restrict__ emb) {
    int row = blockIdx.x * 8 + (threadIdx.x >> 5);
    int lane = threadIdx.x & 31;
    int idx = qp[row];
    float4 v = *(const float4*)(emb + (size_t)idx * 128 + lane * 4);
    *(float4*)(d_q + (size_t)row * 128 + lane * 4) = v;
    *(__half2*)(d_q16  + (size_t)row * 128 + lane * 4)     = __floats2half2_rn(v.x, v.y);
    *(__half2*)(d_q16  + (size_t)row * 128 + lane * 4 + 2) = __floats2half2_rn(v.z, v.w);
    *(__half2*)(d_hl16 + (size_t)row * 128 + lane * 4)     = __floats2half2_rn(-v.x, -v.y);
    *(__half2*)(d_hl16 + (size_t)row * 128 + lane * 4 + 2) = __floats2half2_rn(-v.z, -v.w);
}

// ---------------- N-looped fp16 GEMM: block = 128 rows, loops all N tiles ----------------
// mode 0: Gbuf  = A@B.T + bsum          (A=q16,  B=Wc16)
// mode 1: gates = A@B.T + Gbuf          (A=-q16 in hl16, B=W116)   [step 0]
// mode 2: gates = A@B.T + Gbuf + attn@S2
// last=1: only tiles {0,2,4,6}; packed output width 512.
__global__ void __launch_bounds__(256, 2) k_gates(const __half* __restrict__ A,
                                                  const __half* __restrict__ B,
                                                  int mode, int last) {
    extern __shared__ char smraw[];
    __half* As  = (__half*)smraw;
    __half* Bs  = (__half*)(smraw + OFF_BS);
    float* sS2  = (float*)(smraw + OFF_SS2);
    float* sAt  = (float*)(smraw + OFF_SAT);
    float* sBias= (float*)(smraw + OFF_BIAS);

    int by = blockIdx.x;
    int tid = threadIdx.x, lane = tid & 31, warp = tid >> 5;
    int g = lane >> 2, tg = lane & 3;
    int wm = warp >> 2, wn = warp & 3;          // 2(M) x 4(N); warp tile 64 x 32

    const __half* Ag = A + (size_t)by * 128 * 128;

    // A tile resident for all N iterations
    #pragma unroll
    for (int it = 0; it < 8; it++) {
        int i = tid + it * 256; int r = i >> 4, c8 = (i & 15) << 3;
        *(uint4*)(As + r * SST + c8) = *(const uint4*)(Ag + r * 128 + c8);
    }
    if (mode == 2) {
        for (int i = tid; i < FEW * G4; i += 256) sS2[i] = d_S2[i];
        for (int i = tid; i < 128 * FEW; i += 256) {
            int r = i / FEW, f = i - r * FEW;
            sAt[i] = d_attn[(size_t)(by * 128 + r) * 8 + f];
        }
    }
    if (mode == 0) {
        for (int i = tid; i < G4; i += 256) sBias[i] = d_bsum[i];
    }

    int niter = last ? 4 : 8;
    for (int iter = 0; iter < niter; iter++) {
        int nn = last ? iter * 2 : iter;
        __syncthreads();                         // prev MMA done reading Bs (and As ready)
        const __half* Bg = B + (size_t)nn * 128 * 128;
        #pragma unroll
        for (int it = 0; it < 8; it++) {
            int i = tid + it * 256; int r = i >> 4, c8 = (i & 15) << 3;
            *(uint4*)(Bs + r * SST + c8) = *(const uint4*)(Bg + r * 128 + c8);
        }
        __syncthreads();

        float acc[4][4][4];
        #pragma unroll
        for (int mi = 0; mi < 4; mi++)
            #pragma unroll
            for (int ni = 0; ni < 4; ni++)
                #pragma unroll
                for (int r = 0; r < 4; r++) acc[mi][ni][r] = 0.f;

        #pragma unroll
        for (int kk = 0; kk < 8; kk++) {
            int c0 = kk * 16 + 2 * tg;
            unsigned a[4][4];
            #pragma unroll
            for (int mi = 0; mi < 4; mi++) {
                const __half* p = As + (wm * 64 + mi * 16 + g) * SST + c0;
                a[mi][0] = *(const unsigned*)(p);
                a[mi][1] = *(const unsigned*)(p + 8 * SST);
                a[mi][2] = *(const unsigned*)(p + 8);
                a[mi][3] = *(const unsigned*)(p + 8 * SST + 8);
            }
            #pragma unroll
            for (int ni = 0; ni < 4; ni++) {
                const __half* p = Bs + (wn * 32 + ni * 8 + g) * SST + c0;
                unsigned b0 = *(const unsigned*)(p);
                unsigned b1 = *(const unsigned*)(p + 8);
                #pragma unroll
                for (int mi = 0; mi < 4; mi++)
                    mma_f16(acc[mi][ni], a[mi], b0, b1);
            }
        }

        // epilogue for this N tile (registers + global only)
        int outbase = last ? iter * 128 : nn * 128;
        int W = last ? 512 : G4;
        #pragma unroll
        for (int mi = 0; mi < 4; mi++) {
            #pragma unroll
            for (int ni = 0; ni < 4; ni++) {
                int rl0 = wm * 64 + mi * 16 + g;
                int cit = wn * 32 + ni * 8 + 2 * tg;
                int gcol = nn * 128 + cit;
                #pragma unroll
                for (int rr = 0; rr < 2; rr++) {
                    int rl = rl0 + rr * 8;
                    size_t row = (size_t)(by * 128 + rl);
                    float x0 = acc[mi][ni][rr * 2 + 0];
                    float x1 = acc[mi][ni][rr * 2 + 1];
                    if (mode == 0) {
                        x0 += sBias[gcol]; x1 += sBias[gcol + 1];
                        *(__half2*)(d_Gbuf + row * G4 + gcol) = __floats2half2_rn(x0, x1);
                    } else {
                        __half2 gb2 = *(const __half2*)(d_Gbuf + row * G4 + gcol);
                        float2 gf = __half22float2(gb2);
                        x0 += gf.x; x1 += gf.y;
                        if (mode == 2) {
                            #pragma unroll
                            for (int f = 0; f < FEW; f++) {
                                float av = sAt[rl * FEW + f];
                                x0 = fmaf(av, sS2[f * G4 + gcol], x0);
                                x1 = fmaf(av, sS2[f * G4 + gcol + 1], x1);
                            }
                        }
                        *(__half2*)(d_gates + row * W + outbase + cit) = __floats2half2_rn(x0, x1);
                    }
                }
            }
        }
    }
}

// ---------------- elementwise LSTM update + attention softmax ----------------
__global__ void __launch_bounds__(256) k_lstm(int first) {
    __shared__ float sSg[FEW * 128];
    for (int i = threadIdx.x; i < FEW * 128; i += 256) sSg[i] = d_SG[i];
    __syncthreads();
    int row = blockIdx.x * 8 + (threadIdx.x >> 5);
    int lane = threadIdx.x & 31;
    const __half* gr = d_gates + (size_t)row * 1024;
    float part[FEW] = {0.f, 0.f, 0.f, 0.f, 0.f};
    #pragma unroll
    for (int k = 0; k < 8; k++) {
        int j = lane + 32 * k;
        float gi = __half2float(gr[j]);
        float gf = __half2float(gr[256 + j]);
        float gg = __half2float(gr[512 + j]);
        float go = __half2float(gr[768 + j]);
        float co = first ? 0.f : d_c[(size_t)row * 256 + j];
        float cn = fmaf(sigf(gf), co, sigf(gi) * tanhf(gg));
        d_c[(size_t)row * 256 + j] = cn;
        if (k < 4) {
            float hl = sigf(go) * tanhf(cn);
            float hq = __half2float(d_q16[(size_t)row * 128 + j]) + hl;
            d_hl16[(size_t)row * 128 + j] = __float2half_rn(hl);
            #pragma unroll
            for (int f = 0; f < FEW; f++) part[f] = fmaf(hq, sSg[f * 128 + j], part[f]);
        }
    }
    #pragma unroll
    for (int o = 16; o; o >>= 1)
        #pragma unroll
        for (int f = 0; f < FEW; f++) part[f] += __shfl_xor_sync(0xffffffffu, part[f], o);
    if (lane == 0) {
        float m = part[0];
        #pragma unroll
        for (int f = 1; f < FEW; f++) m = fmaxf(m, part[f]);
        float e[FEW], ss = 0.f;
        #pragma unroll
        for (int f = 0; f < FEW; f++) { e[f] = expf(part[f] - m); ss += e[f]; }
        float inv = 1.f / ss;
        #pragma unroll
        for (int f = 0; f < FEW; f++) d_attn[(size_t)row * 8 + f] = e[f] * inv;
    }
}

// last step: packed 512-wide fp16 gates; only c[:128]/hl needed; hl in fp32 for final
__global__ void __launch_bounds__(256) k_lstm_last() {
    int row = blockIdx.x * 8 + (threadIdx.x >> 5);
    int lane = threadIdx.x & 31;
    const __half* gr = d_gates + (size_t)row * 512;
    #pragma unroll
    for (int k = 0; k < 4; k++) {
        int j = lane + 32 * k;
        float gi = __half2float(gr[j]);
        float gf = __half2float(gr[128 + j]);
        float gg = __half2float(gr[256 + j]);
        float go = __half2float(gr[384 + j]);
        float co = d_c[(size_t)row * 256 + j];
        float cn = fmaf(sigf(gf), co, sigf(gi) * tanhf(gg));
        float hl = sigf(go) * tanhf(cn);
        d_hl[(size_t)row * 128 + j] = hl;
    }
}

// ---------------- final: out[b] = mean(hq[2b], hq[2b+1]) . mean_support ----------------
__global__ void k_final(float* __restrict__ out) {
    __shared__ float ms[128];
    int t = threadIdx.x;
    if (t < 128) ms[t] = d_MS[t];
    __syncthreads();
    int b = blockIdx.x * 8 + (t >> 5);
    int lane = t & 31;
    const float* q0 = d_q  + (size_t)b * 256;
    const float* h0 = d_hl + (size_t)b * 256;
    int j = lane * 4;
    float4 qa = *(const float4*)(q0 + j);
    float4 qb = *(const float4*)(q0 + 128 + j);
    float4 ha = *(const float4*)(h0 + j);
    float4 hb = *(const float4*)(h0 + 128 + j);
    float4 m4 = *(const float4*)(ms + j);
    float p = 0.5f * ((qa.x + ha.x + qb.x + hb.x) * m4.x +
                      (qa.y + ha.y + qb.y + hb.y) * m4.y +
                      (qa.z + ha.z + qb.z + hb.z) * m4.z +
                      (qa.w + ha.w + qb.w + hb.w) * m4.w);
    #pragma unroll
    for (int o = 16; o; o >>= 1) p += __shfl_xor_sync(0xffffffffu, p, o);
    if (lane == 0) out[b] = p;
}

// ---------------- launcher ----------------
extern "C" void kernel_launch(void* const* d_in, const int* in_sizes, int n_in,
                              void* d_out, int out_size) {
    const int*   qp  = (const int*)d_in[0];
    const int*   sp  = (const int*)d_in[1];
    const float* emb = (const float*)d_in[2];
    const float* gW  = (const float*)d_in[3];
    const float* gb  = (const float*)d_in[4];
    const float* p1W = (const float*)d_in[5];
    const float* p1b = (const float*)d_in[6];
    const float* p2W = (const float*)d_in[7];
    const float* p2b = (const float*)d_in[8];
    const float* lng = (const float*)d_in[9];
    const float* lnb = (const float*)d_in[10];
    const float* Wih = (const float*)d_in[11];
    const float* Whh = (const float*)d_in[12];
    const float* bih = (const float*)d_in[13];
    const float* bhh = (const float*)d_in[14];
    float* out = (float*)d_out;

    static int attr_set = 0;
    if (!attr_set) {
        cudaFuncSetAttribute(k_gates, cudaFuncAttributeMaxDynamicSharedMemorySize, SMEM_GATES);
        attr_set = 1;
    }

    k_wsum<<<512, 256>>>(Wih, Whh, bih, bhh);
    k_support<<<5, 256>>>(sp, emb, gW, gb, p1W, p1b, p2W, p2b, lng, lnb);
    k_s2mean<<<41, 128>>>(Whh);
    k_gather<<<NQ / 8, 256>>>(qp, emb);

    __half* pQ16; cudaGetSymbolAddress((void**)&pQ16, d_q16);
    __half* pHL;  cudaGetSymbolAddress((void**)&pHL,  d_hl16);
    __half* pWc;  cudaGetSymbolAddress((void**)&pWc,  d_Wc16);
    __half* pW1;  cudaGetSymbolAddress((void**)&pW1,  d_W116);

    // Gbuf = q @ (Wih + W1).T + bsum   (fp16 out)
    k_gates<<<NQ / 128, 256, SMEM_GATES>>>(pQ16, pWc, 0, 0);

    // step 0: gates = Gbuf + (-q)@W1.T  (hl16 holds -q)
    k_gates<<<NQ / 128, 256, SMEM_GATES>>>(pHL, pW1, 1, 0);
    k_lstm<<<NQ / 8, 256>>>(1);

    // steps 1,2: gates = Gbuf + hl@W1.T + attn@S2
    for (int t = 0; t < 2; t++) {
        k_gates<<<NQ / 128, 256, SMEM_GATES>>>(pHL, pW1, 2, 0);
        k_lstm<<<NQ / 8, 256>>>(0);
    }

    // step 3 (last): tiles {0,2,4,6} packed to width 512
    k_gates<<<NQ / 128, 256, SMEM_GATES>>>(pHL, pW1, 2, 1);
    k_lstm_last<<<NQ / 8, 256>>>();

    k_final<<<16384 / 8, 256>>>(out);
}